// round 2
// baseline (speedup 1.0000x reference)
#include <cuda_runtime.h>

#define NB  4
#define NS  2048
#define ND  1024
#define NH  16
#define NDK 64
#define NTOK (NB * NS)   // 8192

// Scratch (static device globals: allocation-free per harness rules)
__device__ float g_q[(size_t)NTOK * ND];
__device__ float g_k[(size_t)NTOK * ND];
__device__ float g_v[(size_t)NTOK * ND];
__device__ float g_ctx[(size_t)NTOK * ND];

// =====================================================================
// SGEMM (NT): out[m,n] = sum_k A[m,k] * W[n,k] + bias[n]
// MODE==1: A = x (arg), z selects {Wq,Wk,Wv}; store permuted to (B,H,S,DK)
// MODE==0: A = g_ctx; store direct to out[m*N + n]
// Tile 128x128x8, 256 threads, 8x8 micro-tile.
// =====================================================================
template <int MODE>
__global__ __launch_bounds__(256, 2)
void sgemm_nt(const float* __restrict__ A,
              const float* __restrict__ W0, const float* __restrict__ bia0,
              const float* __restrict__ W1, const float* __restrict__ bia1,
              const float* __restrict__ W2, const float* __restrict__ bia2,
              float* __restrict__ outp)
{
    const int K = ND, N = ND;
    const float* W;
    const float* bias;
    float* out;
    const float* Ain;
    if (MODE == 1) {
        int z = blockIdx.z;
        W    = (z == 0) ? W0   : (z == 1) ? W1   : W2;
        bias = (z == 0) ? bia0 : (z == 1) ? bia1 : bia2;
        out  = (z == 0) ? g_q  : (z == 1) ? g_k  : g_v;
        Ain  = A;
    } else {
        W = W0; bias = bia0; out = outp; Ain = g_ctx;
    }

    __shared__ float As[8][128];
    __shared__ float Bs[8][128];

    const int tid = threadIdx.x;
    const int tx = tid & 15, ty = tid >> 4;
    const int m0 = blockIdx.y * 128, n0 = blockIdx.x * 128;

    const int lrow = tid >> 1;
    const int lseg = (tid & 1) * 4;
    const float* aP = Ain + (size_t)(m0 + lrow) * K + lseg;
    const float* wP = W   + (size_t)(n0 + lrow) * K + lseg;

    float acc[8][8] = {};

    for (int k0 = 0; k0 < K; k0 += 8) {
        float4 av = *(const float4*)(aP + k0);
        float4 wv = *(const float4*)(wP + k0);
        As[lseg + 0][lrow] = av.x; As[lseg + 1][lrow] = av.y;
        As[lseg + 2][lrow] = av.z; As[lseg + 3][lrow] = av.w;
        Bs[lseg + 0][lrow] = wv.x; Bs[lseg + 1][lrow] = wv.y;
        Bs[lseg + 2][lrow] = wv.z; Bs[lseg + 3][lrow] = wv.w;
        __syncthreads();

        #pragma unroll
        for (int kk = 0; kk < 8; kk++) {
            float ra[8], rb[8];
            *(float4*)&ra[0] = *(const float4*)&As[kk][ty * 8];
            *(float4*)&ra[4] = *(const float4*)&As[kk][ty * 8 + 4];
            *(float4*)&rb[0] = *(const float4*)&Bs[kk][tx * 8];
            *(float4*)&rb[4] = *(const float4*)&Bs[kk][tx * 8 + 4];
            #pragma unroll
            for (int i = 0; i < 8; i++)
                #pragma unroll
                for (int j = 0; j < 8; j++)
                    acc[i][j] += ra[i] * rb[j];
        }
        __syncthreads();
    }

    #pragma unroll
    for (int i = 0; i < 8; i++) {
        int m = m0 + ty * 8 + i;
        int bb = m >> 11;            // m / NS
        int s  = m & (NS - 1);
        #pragma unroll
        for (int j = 0; j < 8; j++) {
            int n = n0 + tx * 8 + j;
            float v = acc[i][j] + bias[n];
            if (MODE == 1) {
                int h = n >> 6, dk = n & 63;
                out[(((size_t)(bb * NH + h)) * NS + s) * NDK + dk] = v;
            } else {
                out[(size_t)m * N + n] = v;
            }
        }
    }
}

// =====================================================================
// Flash attention (fp32, full attention, no mask).
// Block: 64 q-rows for one (b,h). 256 threads as 16x16, 4x4 micro-tile.
// smem: Qs 16K + Ks 16K + Vs 16K = 48K (P reuses Ks region).
// Scale folded into Q load (1/sqrt(64) = 0.125).
// =====================================================================
__global__ __launch_bounds__(256)
void flash_attn()
{
    __shared__ float Qs[64 * 64];
    __shared__ float Ks[64 * 64];
    __shared__ float Vs[64 * 64];
    float* Ps = Ks;   // reuse after scores computed

    const int tid = threadIdx.x;
    const int tx = tid & 15, ty = tid >> 4;
    const int bh = blockIdx.x;     // 0..63
    const int qt = blockIdx.y;     // 0..31

    const float* qb = g_q + (size_t)bh * NS * NDK + (size_t)qt * 64 * NDK;
    const float* kb = g_k + (size_t)bh * NS * NDK;
    const float* vb = g_v + (size_t)bh * NS * NDK;

    {
        const float4* q4 = (const float4*)qb;
        float4* Qs4 = (float4*)Qs;
        for (int e = tid; e < 1024; e += 256) {
            float4 t = q4[e];
            t.x *= 0.125f; t.y *= 0.125f; t.z *= 0.125f; t.w *= 0.125f;
            Qs4[e] = t;
        }
    }

    float m_i[4], l_i[4], O[4][4];
    #pragma unroll
    for (int i = 0; i < 4; i++) {
        m_i[i] = -1e30f; l_i[i] = 0.f;
        #pragma unroll
        for (int j = 0; j < 4; j++) O[i][j] = 0.f;
    }

    for (int kt = 0; kt < NS / 64; kt++) {
        __syncthreads();   // prev iter's Ps/Vs consumed; Qs visible (iter 0)
        {
            const float4* k4 = (const float4*)(kb + (size_t)kt * 64 * NDK);
            const float4* v4 = (const float4*)(vb + (size_t)kt * 64 * NDK);
            float4* Ks4 = (float4*)Ks;
            float4* Vs4 = (float4*)Vs;
            for (int e = tid; e < 1024; e += 256) { Ks4[e] = k4[e]; Vs4[e] = v4[e]; }
        }
        __syncthreads();

        // S = (Q*scale) @ K^T  -> 4x4 per thread
        float sc[4][4] = {};
        #pragma unroll 4
        for (int d = 0; d < 64; d++) {
            float ra[4], rb[4];
            #pragma unroll
            for (int i = 0; i < 4; i++) ra[i] = Qs[(ty * 4 + i) * 64 + d];
            #pragma unroll
            for (int j = 0; j < 4; j++) rb[j] = Ks[(tx * 4 + j) * 64 + d];
            #pragma unroll
            for (int i = 0; i < 4; i++)
                #pragma unroll
                for (int j = 0; j < 4; j++)
                    sc[i][j] += ra[i] * rb[j];
        }

        // Online softmax per row (row group = 16 lanes sharing ty)
        #pragma unroll
        for (int i = 0; i < 4; i++) {
            float rm = fmaxf(fmaxf(sc[i][0], sc[i][1]), fmaxf(sc[i][2], sc[i][3]));
            #pragma unroll
            for (int off = 8; off > 0; off >>= 1)
                rm = fmaxf(rm, __shfl_xor_sync(0xffffffffu, rm, off));
            float mn = fmaxf(m_i[i], rm);
            float corr = __expf(m_i[i] - mn);
            m_i[i] = mn;
            float rs = 0.f;
            #pragma unroll
            for (int j = 0; j < 4; j++) {
                float p = __expf(sc[i][j] - mn);
                sc[i][j] = p;
                rs += p;
            }
            #pragma unroll
            for (int off = 8; off > 0; off >>= 1)
                rs += __shfl_xor_sync(0xffffffffu, rs, off);
            l_i[i] = l_i[i] * corr + rs;
            #pragma unroll
            for (int j = 0; j < 4; j++) O[i][j] *= corr;
        }

        __syncthreads();   // everyone done reading Ks before P overwrites it
        #pragma unroll
        for (int i = 0; i < 4; i++)
            #pragma unroll
            for (int j = 0; j < 4; j++)
                Ps[(ty * 4 + i) * 64 + tx * 4 + j] = sc[i][j];
        __syncthreads();

        // O += P @ V
        #pragma unroll 4
        for (int c = 0; c < 64; c++) {
            float4 rv = *(const float4*)&Vs[c * 64 + tx * 4];
            float rp[4];
            #pragma unroll
            for (int i = 0; i < 4; i++) rp[i] = Ps[(ty * 4 + i) * 64 + c];
            #pragma unroll
            for (int i = 0; i < 4; i++) {
                O[i][0] += rp[i] * rv.x;
                O[i][1] += rp[i] * rv.y;
                O[i][2] += rp[i] * rv.z;
                O[i][3] += rp[i] * rv.w;
            }
        }
    }

    // Normalize and store to g_ctx in (B,S,D) layout
    const int bb = bh >> 4, h = bh & 15;
    #pragma unroll
    for (int i = 0; i < 4; i++) {
        float inv = 1.0f / l_i[i];
        int s = qt * 64 + ty * 4 + i;
        float* dst = g_ctx + ((size_t)(bb * NS + s)) * ND + h * 64 + tx * 4;
        float4 o4 = make_float4(O[i][0] * inv, O[i][1] * inv, O[i][2] * inv, O[i][3] * inv);
        *(float4*)dst = o4;
    }
}

// =====================================================================
extern "C" void kernel_launch(void* const* d_in, const int* in_sizes, int n_in,
                              void* d_out, int out_size)
{
    const float* x  = (const float*)d_in[0];
    const float* Wq = (const float*)d_in[1];
    const float* bq = (const float*)d_in[2];
    const float* Wk = (const float*)d_in[3];
    const float* bk = (const float*)d_in[4];
    const float* Wv = (const float*)d_in[5];
    const float* bv = (const float*)d_in[6];
    const float* Wo = (const float*)d_in[7];
    const float* bo = (const float*)d_in[8];
    float* out = (float*)d_out;

    dim3 gqkv(ND / 128, NTOK / 128, 3);
    sgemm_nt<1><<<gqkv, 256>>>(x, Wq, bq, Wk, bk, Wv, bv, nullptr);

    dim3 gat(NB * NH, NS / 64);
    flash_attn<<<gat, 256>>>();

    dim3 go(ND / 128, NTOK / 128, 1);
    sgemm_nt<0><<<go, 256>>>(nullptr, Wo, bo, nullptr, nullptr, nullptr, nullptr, out);
}

// round 3
// speedup vs baseline: 5.4043x; 5.4043x over previous
#include <cuda_runtime.h>
#include <cstdint>

#define NB  4
#define NS  2048
#define ND  1024
#define NH  16
#define NDK 64
#define NTOK (NB * NS)   // 8192

// Scratch (static device globals: allocation-free per harness rules)
__device__ float g_q[(size_t)NTOK * ND];    // (B,H,S,DK)
__device__ float g_k[(size_t)NTOK * ND];    // (B,H,S,DK)
__device__ float g_v[(size_t)NTOK * ND];    // (B,H,DK,S)  <- transposed!
__device__ float g_ctx[(size_t)NTOK * ND];  // (B,S,D)

__device__ __forceinline__ uint32_t f2tf32(float f) {
    uint32_t u;
    asm("cvt.rna.tf32.f32 %0, %1;" : "=r"(u) : "f"(f));
    return u;
}

// D += A(m16 x k8, row) * B(k8 x n8, col), tf32 inputs, fp32 accum.
// A frag: a0:(g,tig) a1:(g+8,tig) a2:(g,tig+4) a3:(g+8,tig+4)
// B frag: b0:(k=tig,n=g) b1:(k=tig+4,n=g)
// C frag: c0:(g,2t) c1:(g,2t+1) c2:(g+8,2t) c3:(g+8,2t+1)
__device__ __forceinline__ void mma8(float* c, const uint32_t* a, const uint32_t* b) {
    asm volatile("mma.sync.aligned.m16n8k8.row.col.f32.tf32.tf32.f32 "
                 "{%0,%1,%2,%3}, {%4,%5,%6,%7}, {%8,%9}, {%0,%1,%2,%3};"
                 : "+f"(c[0]), "+f"(c[1]), "+f"(c[2]), "+f"(c[3])
                 : "r"(a[0]), "r"(a[1]), "r"(a[2]), "r"(a[3]),
                   "r"(b[0]), "r"(b[1]));
}

// =====================================================================
// tf32 GEMM (NT): out[m,n] = sum_k A[m,k]*W[n,k] + bias[n]
// Block 128x128, 8 warps (4x2), warp tile 32x64. K-step 16, double buffer.
// MODE==1: z selects {Wq,Wk,Wv}; q/k permuted to (B,H,S,DK); v to (B,H,DK,S)
// MODE==0: A = g_ctx, direct store.
// =====================================================================
#define LDA 20   // 16 cols + 4 pad: (20*g+tig) mod 32 is a permutation

template <int MODE>
__global__ __launch_bounds__(256)
void gemm_tf32(const float* __restrict__ A,
               const float* __restrict__ W0, const float* __restrict__ bia0,
               const float* __restrict__ W1, const float* __restrict__ bia1,
               const float* __restrict__ W2, const float* __restrict__ bia2,
               float* __restrict__ outp)
{
    const float *W, *bias, *Ain;
    float* out;
    const int z = (MODE == 1) ? blockIdx.z : 3;
    if (MODE == 1) {
        W    = (z == 0) ? W0   : (z == 1) ? W1   : W2;
        bias = (z == 0) ? bia0 : (z == 1) ? bia1 : bia2;
        out  = (z == 0) ? g_q  : (z == 1) ? g_k  : g_v;
        Ain  = A;
    } else {
        W = W0; bias = bia0; out = outp; Ain = g_ctx;
    }

    __shared__ uint32_t As[2][128 * LDA];
    __shared__ uint32_t Bs[2][128 * LDA];

    const int tid  = threadIdx.x;
    const int warp = tid >> 5, lane = tid & 31;
    const int g = lane >> 2, tig = lane & 3;
    const int wm = warp >> 1, wn = warp & 1;       // 4 x 2 warp grid
    const int m0 = blockIdx.y * 128, n0 = blockIdx.x * 128;

    // gmem->smem mapping: float4 elems e = tid + i*256, row=e>>2, colseg=(e&3)*4
    const int r0 = tid >> 2;
    const int cs = (tid & 3) * 4;
    const float* aP = Ain + (size_t)(m0 + r0) * ND + cs;
    const float* wP = W   + (size_t)(n0 + r0) * ND + cs;

    float acc[2][8][4];
    #pragma unroll
    for (int mf = 0; mf < 2; mf++)
        #pragma unroll
        for (int nf = 0; nf < 8; nf++)
            #pragma unroll
            for (int i = 0; i < 4; i++) acc[mf][nf][i] = 0.f;

    // prologue: fill stage 0
    {
        float4 a0v = *(const float4*)(aP);
        float4 a1v = *(const float4*)(aP + (size_t)64 * ND);
        float4 w0v = *(const float4*)(wP);
        float4 w1v = *(const float4*)(wP + (size_t)64 * ND);
        uint32_t* a_s = &As[0][r0 * LDA + cs];
        uint32_t* b_s = &Bs[0][r0 * LDA + cs];
        a_s[0] = f2tf32(a0v.x); a_s[1] = f2tf32(a0v.y); a_s[2] = f2tf32(a0v.z); a_s[3] = f2tf32(a0v.w);
        a_s[64*LDA+0] = f2tf32(a1v.x); a_s[64*LDA+1] = f2tf32(a1v.y); a_s[64*LDA+2] = f2tf32(a1v.z); a_s[64*LDA+3] = f2tf32(a1v.w);
        b_s[0] = f2tf32(w0v.x); b_s[1] = f2tf32(w0v.y); b_s[2] = f2tf32(w0v.z); b_s[3] = f2tf32(w0v.w);
        b_s[64*LDA+0] = f2tf32(w1v.x); b_s[64*LDA+1] = f2tf32(w1v.y); b_s[64*LDA+2] = f2tf32(w1v.z); b_s[64*LDA+3] = f2tf32(w1v.w);
    }
    __syncthreads();

    for (int kt = 0; kt < 64; kt++) {
        const int cur = kt & 1;

        // prefetch next K-slab into registers
        float4 pa0, pa1, pw0, pw1;
        if (kt < 63) {
            const float* ap = aP + (kt + 1) * 16;
            const float* wp = wP + (kt + 1) * 16;
            pa0 = *(const float4*)(ap);
            pa1 = *(const float4*)(ap + (size_t)64 * ND);
            pw0 = *(const float4*)(wp);
            pw1 = *(const float4*)(wp + (size_t)64 * ND);
        }

        // compute: two k8 steps on stage cur
        #pragma unroll
        for (int kk = 0; kk < 2; kk++) {
            uint32_t af[2][4], bf[8][2];
            const uint32_t* as = &As[cur][0];
            const uint32_t* bs = &Bs[cur][0];
            #pragma unroll
            for (int mf = 0; mf < 2; mf++) {
                const int row = wm * 32 + mf * 16;
                af[mf][0] = as[(row + g    ) * LDA + kk * 8 + tig    ];
                af[mf][1] = as[(row + g + 8) * LDA + kk * 8 + tig    ];
                af[mf][2] = as[(row + g    ) * LDA + kk * 8 + tig + 4];
                af[mf][3] = as[(row + g + 8) * LDA + kk * 8 + tig + 4];
            }
            #pragma unroll
            for (int nf = 0; nf < 8; nf++) {
                const int row = wn * 64 + nf * 8 + g;
                bf[nf][0] = bs[row * LDA + kk * 8 + tig    ];
                bf[nf][1] = bs[row * LDA + kk * 8 + tig + 4];
            }
            #pragma unroll
            for (int mf = 0; mf < 2; mf++)
                #pragma unroll
                for (int nf = 0; nf < 8; nf++)
                    mma8(acc[mf][nf], af[mf], bf[nf]);
        }

        // store prefetched slab into other stage
        if (kt < 63) {
            const int nxt = cur ^ 1;
            uint32_t* a_s = &As[nxt][r0 * LDA + cs];
            uint32_t* b_s = &Bs[nxt][r0 * LDA + cs];
            a_s[0] = f2tf32(pa0.x); a_s[1] = f2tf32(pa0.y); a_s[2] = f2tf32(pa0.z); a_s[3] = f2tf32(pa0.w);
            a_s[64*LDA+0] = f2tf32(pa1.x); a_s[64*LDA+1] = f2tf32(pa1.y); a_s[64*LDA+2] = f2tf32(pa1.z); a_s[64*LDA+3] = f2tf32(pa1.w);
            b_s[0] = f2tf32(pw0.x); b_s[1] = f2tf32(pw0.y); b_s[2] = f2tf32(pw0.z); b_s[3] = f2tf32(pw0.w);
            b_s[64*LDA+0] = f2tf32(pw1.x); b_s[64*LDA+1] = f2tf32(pw1.y); b_s[64*LDA+2] = f2tf32(pw1.z); b_s[64*LDA+3] = f2tf32(pw1.w);
        }
        __syncthreads();
    }

    // epilogue
    #pragma unroll
    for (int mf = 0; mf < 2; mf++) {
        #pragma unroll
        for (int i2 = 0; i2 < 2; i2++) {
            const int m = m0 + wm * 32 + mf * 16 + g + i2 * 8;
            const int bb = m >> 11;          // m / NS
            const int s  = m & (NS - 1);
            #pragma unroll
            for (int nf = 0; nf < 8; nf++) {
                const int n = n0 + wn * 64 + nf * 8 + tig * 2;
                const float v0 = acc[mf][nf][i2 * 2 + 0] + bias[n];
                const float v1 = acc[mf][nf][i2 * 2 + 1] + bias[n + 1];
                if (MODE == 0) {
                    *(float2*)&out[(size_t)m * ND + n] = make_float2(v0, v1);
                } else {
                    const int h = n >> 6, dk = n & 63;
                    if (z < 2) {   // q, k: (B,H,S,DK)
                        *(float2*)&out[(((size_t)(bb * NH + h)) * NS + s) * NDK + dk] =
                            make_float2(v0, v1);
                    } else {       // v: (B,H,DK,S) transposed
                        const size_t base = ((size_t)(bb * NH + h) * NDK + dk) * NS + s;
                        out[base]      = v0;
                        out[base + NS] = v1;
                    }
                }
            }
        }
    }
}

// =====================================================================
// tf32 flash attention. Block: 64 q-rows of one (b,h); 4 warps x 16 rows.
// K tile 64, smem stride 68 (bank = 4g+tig: conflict-free frag loads).
// P reuses Ks buffer. V read from transposed (B,H,DK,S) layout.
// =====================================================================
#define LDK 68

__global__ __launch_bounds__(128)
void flash_tf32()
{
    __shared__ uint32_t Ks[64 * LDK];   // K tile; reused as P tile
    __shared__ uint32_t Vt[64 * LDK];   // V^T tile: [dk][kv]

    const int tid = threadIdx.x;
    const int w = tid >> 5, lane = tid & 31;
    const int g = lane >> 2, tig = lane & 3;
    const int bh = blockIdx.x;   // 0..63
    const int qt = blockIdx.y;   // 0..31

    const float* qb = g_q + (size_t)bh * NS * NDK + (size_t)qt * 64 * NDK;
    const float* kb = g_k + (size_t)bh * NS * NDK;
    const float* vb = g_v + (size_t)bh * NDK * NS;

    // Q fragments (scale folded): warp w owns q-rows w*16 .. w*16+15
    uint32_t Qa[8][4];
    #pragma unroll
    for (int kf = 0; kf < 8; kf++) {
        const float* q0 = qb + (w * 16 + g    ) * NDK + kf * 8 + tig;
        const float* q1 = qb + (w * 16 + g + 8) * NDK + kf * 8 + tig;
        Qa[kf][0] = f2tf32(0.125f * q0[0]);
        Qa[kf][1] = f2tf32(0.125f * q1[0]);
        Qa[kf][2] = f2tf32(0.125f * q0[4]);
        Qa[kf][3] = f2tf32(0.125f * q1[4]);
    }

    float O[8][4];
    #pragma unroll
    for (int nf = 0; nf < 8; nf++)
        #pragma unroll
        for (int i = 0; i < 4; i++) O[nf][i] = 0.f;
    float mrow0 = -1e30f, mrow1 = -1e30f, lrow0 = 0.f, lrow1 = 0.f;

    for (int kt = 0; kt < NS / 64; kt++) {
        __syncthreads();   // prior iter's P/V consumers done
        // load K tile [kv][dk] and V^T tile [dk][kv]
        #pragma unroll
        for (int i = 0; i < 8; i++) {
            const int e = tid + i * 128;
            const int row = e >> 4, c2 = (e & 15) * 4;
            float4 kv4 = *(const float4*)(kb + (size_t)(kt * 64 + row) * NDK + c2);
            float4 vv4 = *(const float4*)(vb + (size_t)row * NS + kt * 64 + c2);
            uint32_t* ks = &Ks[row * LDK + c2];
            uint32_t* vs = &Vt[row * LDK + c2];
            ks[0] = f2tf32(kv4.x); ks[1] = f2tf32(kv4.y); ks[2] = f2tf32(kv4.z); ks[3] = f2tf32(kv4.w);
            vs[0] = f2tf32(vv4.x); vs[1] = f2tf32(vv4.y); vs[2] = f2tf32(vv4.z); vs[3] = f2tf32(vv4.w);
        }
        __syncthreads();

        // S = Q @ K^T  (m16 x n64 per warp)
        float S[8][4];
        #pragma unroll
        for (int nf = 0; nf < 8; nf++)
            #pragma unroll
            for (int i = 0; i < 4; i++) S[nf][i] = 0.f;
        #pragma unroll
        for (int kf = 0; kf < 8; kf++) {
            #pragma unroll
            for (int nf = 0; nf < 8; nf++) {
                uint32_t b[2];
                b[0] = Ks[(nf * 8 + g) * LDK + kf * 8 + tig    ];
                b[1] = Ks[(nf * 8 + g) * LDK + kf * 8 + tig + 4];
                mma8(S[nf], Qa[kf], b);
            }
        }

        // online softmax: thread owns rows g (c0,c1) and g+8 (c2,c3)
        float mx0 = -1e30f, mx1 = -1e30f;
        #pragma unroll
        for (int nf = 0; nf < 8; nf++) {
            mx0 = fmaxf(mx0, fmaxf(S[nf][0], S[nf][1]));
            mx1 = fmaxf(mx1, fmaxf(S[nf][2], S[nf][3]));
        }
        mx0 = fmaxf(mx0, __shfl_xor_sync(0xffffffffu, mx0, 1));
        mx0 = fmaxf(mx0, __shfl_xor_sync(0xffffffffu, mx0, 2));
        mx1 = fmaxf(mx1, __shfl_xor_sync(0xffffffffu, mx1, 1));
        mx1 = fmaxf(mx1, __shfl_xor_sync(0xffffffffu, mx1, 2));
        const float mn0 = fmaxf(mrow0, mx0), mn1 = fmaxf(mrow1, mx1);
        const float cr0 = __expf(mrow0 - mn0), cr1 = __expf(mrow1 - mn1);
        mrow0 = mn0; mrow1 = mn1;
        float s0 = 0.f, s1 = 0.f;
        #pragma unroll
        for (int nf = 0; nf < 8; nf++) {
            S[nf][0] = __expf(S[nf][0] - mn0); s0 += S[nf][0];
            S[nf][1] = __expf(S[nf][1] - mn0); s0 += S[nf][1];
            S[nf][2] = __expf(S[nf][2] - mn1); s1 += S[nf][2];
            S[nf][3] = __expf(S[nf][3] - mn1); s1 += S[nf][3];
        }
        s0 += __shfl_xor_sync(0xffffffffu, s0, 1);
        s0 += __shfl_xor_sync(0xffffffffu, s0, 2);
        s1 += __shfl_xor_sync(0xffffffffu, s1, 1);
        s1 += __shfl_xor_sync(0xffffffffu, s1, 2);
        lrow0 = lrow0 * cr0 + s0;
        lrow1 = lrow1 * cr1 + s1;
        #pragma unroll
        for (int nf = 0; nf < 8; nf++) {
            O[nf][0] *= cr0; O[nf][1] *= cr0;
            O[nf][2] *= cr1; O[nf][3] *= cr1;
        }

        __syncthreads();   // all warps done reading Ks
        // write P (tf32) over Ks: rows w*16+{g,g+8}, cols nf*8+tig*2
        uint32_t* Ps = Ks;
        #pragma unroll
        for (int nf = 0; nf < 8; nf++) {
            const int c = nf * 8 + tig * 2;
            Ps[(w * 16 + g    ) * LDK + c    ] = f2tf32(S[nf][0]);
            Ps[(w * 16 + g    ) * LDK + c + 1] = f2tf32(S[nf][1]);
            Ps[(w * 16 + g + 8) * LDK + c    ] = f2tf32(S[nf][2]);
            Ps[(w * 16 + g + 8) * LDK + c + 1] = f2tf32(S[nf][3]);
        }
        __syncthreads();

        // O += P @ V
        #pragma unroll
        for (int kf = 0; kf < 8; kf++) {
            uint32_t a[4];
            a[0] = Ps[(w * 16 + g    ) * LDK + kf * 8 + tig    ];
            a[1] = Ps[(w * 16 + g + 8) * LDK + kf * 8 + tig    ];
            a[2] = Ps[(w * 16 + g    ) * LDK + kf * 8 + tig + 4];
            a[3] = Ps[(w * 16 + g + 8) * LDK + kf * 8 + tig + 4];
            #pragma unroll
            for (int nf = 0; nf < 8; nf++) {
                uint32_t b[2];
                b[0] = Vt[(nf * 8 + g) * LDK + kf * 8 + tig    ];
                b[1] = Vt[(nf * 8 + g) * LDK + kf * 8 + tig + 4];
                mma8(O[nf], a, b);
            }
        }
    }

    // normalize + store to g_ctx (B,S,D)
    const float i0 = 1.0f / lrow0, i1 = 1.0f / lrow1;
    const int bb = bh >> 4, h = bh & 15;
    const int s0r = qt * 64 + w * 16 + g;
    const int s1r = s0r + 8;
    #pragma unroll
    for (int nf = 0; nf < 8; nf++) {
        const int col = h * 64 + nf * 8 + tig * 2;
        *(float2*)&g_ctx[(size_t)(bb * NS + s0r) * ND + col] =
            make_float2(O[nf][0] * i0, O[nf][1] * i0);
        *(float2*)&g_ctx[(size_t)(bb * NS + s1r) * ND + col] =
            make_float2(O[nf][2] * i1, O[nf][3] * i1);
    }
}

// =====================================================================
extern "C" void kernel_launch(void* const* d_in, const int* in_sizes, int n_in,
                              void* d_out, int out_size)
{
    const float* x  = (const float*)d_in[0];
    const float* Wq = (const float*)d_in[1];
    const float* bq = (const float*)d_in[2];
    const float* Wk = (const float*)d_in[3];
    const float* bk = (const float*)d_in[4];
    const float* Wv = (const float*)d_in[5];
    const float* bv = (const float*)d_in[6];
    const float* Wo = (const float*)d_in[7];
    const float* bo = (const float*)d_in[8];
    float* out = (float*)d_out;

    dim3 gqkv(ND / 128, NTOK / 128, 3);
    gemm_tf32<1><<<gqkv, 256>>>(x, Wq, bq, Wk, bk, Wv, bv, nullptr);

    dim3 gat(NB * NH, NS / 64);
    flash_tf32<<<gat, 128>>>();

    dim3 go(ND / 128, NTOK / 128, 1);
    gemm_tf32<0><<<go, 256>>>(nullptr, Wo, bo, nullptr, nullptr, nullptr, nullptr, out);
}

// round 7
// speedup vs baseline: 5.8056x; 1.0743x over previous
#include <cuda_runtime.h>
#include <cstdint>

#define NB  4
#define NS  2048
#define ND  1024
#define NH  16
#define NDK 64
#define NTOK (NB * NS)   // 8192

// Scratch (static device globals: allocation-free per harness rules)
__device__ float g_q[(size_t)NTOK * ND];    // (B,H,S,DK)
__device__ float g_k[(size_t)NTOK * ND];    // (B,H,S,DK)
__device__ float g_v[(size_t)NTOK * ND];    // (B,H,DK,S)  <- transposed!
__device__ float g_ctx[(size_t)NTOK * ND];  // (B,S,D)

// ---------------- helpers ----------------
__device__ __forceinline__ uint32_t f2tf32(float f) {
    uint32_t u;
    asm("cvt.rna.tf32.f32 %0, %1;" : "=r"(u) : "f"(f));
    return u;
}
__device__ __forceinline__ uint32_t smem_u32(const void* p) {
    uint32_t a;
    asm("{ .reg .u64 t; cvta.to.shared.u64 t, %1; cvt.u32.u64 %0, t; }" : "=r"(a) : "l"(p));
    return a;
}
__device__ __forceinline__ void cp16(uint32_t dst, const void* src) {
    asm volatile("cp.async.cg.shared.global [%0], [%1], 16;" :: "r"(dst), "l"(src));
}
#define CP_COMMIT() asm volatile("cp.async.commit_group;" ::: "memory")
#define CP_WAIT0()  asm volatile("cp.async.wait_group 0;" ::: "memory")

// D += A(m16 x k8, row) * B(k8 x n8, col), tf32 inputs, fp32 accum.
// A frag: a0:(g,tig) a1:(g+8,tig) a2:(g,tig+4) a3:(g+8,tig+4)
// B frag: b0:(k=tig,n=g) b1:(k=tig+4,n=g)
// C frag: c0:(g,2t) c1:(g,2t+1) c2:(g+8,2t) c3:(g+8,2t+1)
__device__ __forceinline__ void mma8(float* c, const uint32_t* a, const uint32_t* b) {
    asm volatile("mma.sync.aligned.m16n8k8.row.col.f32.tf32.tf32.f32 "
                 "{%0,%1,%2,%3}, {%4,%5,%6,%7}, {%8,%9}, {%0,%1,%2,%3};"
                 : "+f"(c[0]), "+f"(c[1]), "+f"(c[2]), "+f"(c[3])
                 : "r"(a[0]), "r"(a[1]), "r"(a[2]), "r"(a[3]),
                   "r"(b[0]), "r"(b[1]));
}

// =====================================================================
// tf32 GEMM (NT): out[m,n] = sum_k A[m,k]*W[n,k] + bias[n]
// Block 128x128, 4 warps (2x2), warp tile 64x64. k-slab 16, cp.async
// double buffer of RAW fp32; cvt to tf32 after LDS (per fragment).
// MODE==1: z selects {Wq,Wk,Wv}; q/k -> (B,H,S,DK); v -> (B,H,DK,S)
// MODE==0: A = g_ctx, direct store.
// =====================================================================
#define LDA 20   // 16 data + 4 pad words: (20g+tig) mod 32 is a permutation

template <int MODE>
__global__ __launch_bounds__(128, 2)
void gemm_tf32(const float* __restrict__ A,
               const float* __restrict__ W0, const float* __restrict__ bia0,
               const float* __restrict__ W1, const float* __restrict__ bia1,
               const float* __restrict__ W2, const float* __restrict__ bia2,
               float* __restrict__ outp)
{
    const float *W, *bias, *Ain;
    float* out;
    const int z = (MODE == 1) ? blockIdx.z : 3;
    if (MODE == 1) {
        W    = (z == 0) ? W0   : (z == 1) ? W1   : W2;
        bias = (z == 0) ? bia0 : (z == 1) ? bia1 : bia2;
        out  = (z == 0) ? g_q  : (z == 1) ? g_k  : g_v;
        Ain  = A;
    } else {
        W = W0; bias = bia0; out = outp; Ain = g_ctx;
    }

    __shared__ __align__(16) uint32_t As[2][128 * LDA];   // raw fp32 bits
    __shared__ __align__(16) uint32_t Bs[2][128 * LDA];

    const int tid  = threadIdx.x;
    const int warp = tid >> 5, lane = tid & 31;
    const int g = lane >> 2, tig = lane & 3;
    const int wm = warp >> 1, wn = warp & 1;          // 2x2 warp grid, 64x64 each
    const int m0 = blockIdx.y * 128, n0 = blockIdx.x * 128;

    const uint32_t aS[2] = { smem_u32(&As[0][0]), smem_u32(&As[1][0]) };
    const uint32_t bS[2] = { smem_u32(&Bs[0][0]), smem_u32(&Bs[1][0]) };

    float acc[4][8][4];
    #pragma unroll
    for (int mf = 0; mf < 4; mf++)
        #pragma unroll
        for (int nf = 0; nf < 8; nf++)
            #pragma unroll
            for (int i = 0; i < 4; i++) acc[mf][nf][i] = 0.f;

    // per-thread fill: 4 A-chunks + 4 B-chunks of 16B per slab
    const int chr[4] = { (tid + 0) >> 2, (tid + 128) >> 2, (tid + 256) >> 2, (tid + 384) >> 2 };
    const int chc = (tid & 3) * 4;

    // prologue: stage 0
    #pragma unroll
    for (int i = 0; i < 4; i++) {
        cp16(aS[0] + (uint32_t)(chr[i] * LDA + chc) * 4u,
             Ain + (size_t)(m0 + chr[i]) * ND + chc);
        cp16(bS[0] + (uint32_t)(chr[i] * LDA + chc) * 4u,
             W   + (size_t)(n0 + chr[i]) * ND + chc);
    }
    CP_COMMIT();

    for (int it = 0; it < 64; it++) {
        const int cur = it & 1;
        CP_WAIT0();
        __syncthreads();
        if (it < 63) {
            const int k0 = (it + 1) * 16;
            const int nxt = cur ^ 1;
            #pragma unroll
            for (int i = 0; i < 4; i++) {
                cp16(aS[nxt] + (uint32_t)(chr[i] * LDA + chc) * 4u,
                     Ain + (size_t)(m0 + chr[i]) * ND + k0 + chc);
                cp16(bS[nxt] + (uint32_t)(chr[i] * LDA + chc) * 4u,
                     W   + (size_t)(n0 + chr[i]) * ND + k0 + chc);
            }
            CP_COMMIT();
        }

        const uint32_t* as = As[cur];
        const uint32_t* bs = Bs[cur];
        #pragma unroll
        for (int kk = 0; kk < 2; kk++) {
            uint32_t af[4][4], bf[8][2];
            #pragma unroll
            for (int mf = 0; mf < 4; mf++) {
                const int row = wm * 64 + mf * 16;
                af[mf][0] = f2tf32(__uint_as_float(as[(row + g    ) * LDA + kk * 8 + tig    ]));
                af[mf][1] = f2tf32(__uint_as_float(as[(row + g + 8) * LDA + kk * 8 + tig    ]));
                af[mf][2] = f2tf32(__uint_as_float(as[(row + g    ) * LDA + kk * 8 + tig + 4]));
                af[mf][3] = f2tf32(__uint_as_float(as[(row + g + 8) * LDA + kk * 8 + tig + 4]));
            }
            #pragma unroll
            for (int nf = 0; nf < 8; nf++) {
                const int row = wn * 64 + nf * 8 + g;
                bf[nf][0] = f2tf32(__uint_as_float(bs[row * LDA + kk * 8 + tig    ]));
                bf[nf][1] = f2tf32(__uint_as_float(bs[row * LDA + kk * 8 + tig + 4]));
            }
            #pragma unroll
            for (int mf = 0; mf < 4; mf++)
                #pragma unroll
                for (int nf = 0; nf < 8; nf++)
                    mma8(acc[mf][nf], af[mf], bf[nf]);
        }
    }

    // epilogue
    #pragma unroll
    for (int mf = 0; mf < 4; mf++) {
        #pragma unroll
        for (int i2 = 0; i2 < 2; i2++) {
            const int m = m0 + wm * 64 + mf * 16 + g + i2 * 8;
            const int bb = m >> 11;
            const int s  = m & (NS - 1);
            #pragma unroll
            for (int nf = 0; nf < 8; nf++) {
                const int n = n0 + wn * 64 + nf * 8 + tig * 2;
                const float v0 = acc[mf][nf][i2 * 2 + 0] + bias[n];
                const float v1 = acc[mf][nf][i2 * 2 + 1] + bias[n + 1];
                if (MODE == 0) {
                    *(float2*)&out[(size_t)m * ND + n] = make_float2(v0, v1);
                } else {
                    const int h = n >> 6, dk = n & 63;
                    if (z < 2) {   // q,k: (B,H,S,DK)
                        *(float2*)&out[(((size_t)(bb * NH + h)) * NS + s) * NDK + dk] =
                            make_float2(v0, v1);
                    } else {       // v: (B,H,DK,S)
                        const size_t base = ((size_t)(bb * NH + h) * NDK + dk) * NS + s;
                        out[base]      = v0;
                        out[base + NS] = v1;
                    }
                }
            }
        }
    }
}

// =====================================================================
// tf32 flash attention. Block: 256 q-rows of one (b,h); 8 warps x m32.
// KV tile 64. P never touches smem: C-frag -> A-frag conversion is done
// with warp shuffles (P rows needed by a warp are exactly the rows that
// warp computed). Smem: Ks + Vt = 34.8 KB.
// =====================================================================
#define LDK 68

__global__ __launch_bounds__(256)
void flash_tf32()
{
    __shared__ __align__(16) uint32_t Ks[64 * LDK];   // K tile [kv][dk]
    __shared__ __align__(16) uint32_t Vt[64 * LDK];   // V^T tile [dk][kv]

    const int tid = threadIdx.x;
    const int w = tid >> 5, lane = tid & 31;
    const int g = lane >> 2, tig = lane & 3;
    const int bh = blockIdx.x;   // 0..63
    const int qt = blockIdx.y;   // 0..7  (256 rows each)

    // shuffle source lanes for C->A fragment conversion
    const int s0l = (lane & ~3) | (tig >> 1);   // for col kf*8+tig
    const int s2l = s0l + 2;                    // for col kf*8+tig+4
    const bool par = (tig & 1);

    const float* qb = g_q + (size_t)bh * NS * NDK + (size_t)qt * 256 * NDK;
    const float* kb = g_k + (size_t)bh * NS * NDK;
    const float* vb = g_v + (size_t)bh * NDK * NS;

    // Q fragments (scale folded): warp w owns q-rows w*32 .. w*32+31
    uint32_t Qa[2][8][4];
    #pragma unroll
    for (int mf = 0; mf < 2; mf++)
        #pragma unroll
        for (int kf = 0; kf < 8; kf++) {
            const float* q0 = qb + (w * 32 + mf * 16 + g) * NDK + kf * 8 + tig;
            const float* q1 = q0 + 8 * NDK;
            Qa[mf][kf][0] = f2tf32(0.125f * q0[0]);
            Qa[mf][kf][1] = f2tf32(0.125f * q1[0]);
            Qa[mf][kf][2] = f2tf32(0.125f * q0[4]);
            Qa[mf][kf][3] = f2tf32(0.125f * q1[4]);
        }

    float O[2][8][4];
    #pragma unroll
    for (int mf = 0; mf < 2; mf++)
        #pragma unroll
        for (int nf = 0; nf < 8; nf++)
            #pragma unroll
            for (int i = 0; i < 4; i++) O[mf][nf][i] = 0.f;
    float mr[2][2], lr[2][2];
    #pragma unroll
    for (int mf = 0; mf < 2; mf++) {
        mr[mf][0] = mr[mf][1] = -1e30f;
        lr[mf][0] = lr[mf][1] = 0.f;
    }

    for (int kt = 0; kt < NS / 64; kt++) {
        __syncthreads();   // prior iter's Ks/Vt consumers done
        #pragma unroll
        for (int i = 0; i < 4; i++) {
            const int e = tid + i * 256;
            const int row = e >> 4, c2 = (e & 15) * 4;
            float4 kv4 = *(const float4*)(kb + (size_t)(kt * 64 + row) * NDK + c2);
            float4 vv4 = *(const float4*)(vb + (size_t)row * NS + kt * 64 + c2);
            uint32_t* ks = &Ks[row * LDK + c2];
            uint32_t* vs = &Vt[row * LDK + c2];
            ks[0] = f2tf32(kv4.x); ks[1] = f2tf32(kv4.y); ks[2] = f2tf32(kv4.z); ks[3] = f2tf32(kv4.w);
            vs[0] = f2tf32(vv4.x); vs[1] = f2tf32(vv4.y); vs[2] = f2tf32(vv4.z); vs[3] = f2tf32(vv4.w);
        }
        __syncthreads();

        // S = Q @ K^T  (m32 x n64 per warp); B frags shared across mf
        float S[2][8][4];
        #pragma unroll
        for (int mf = 0; mf < 2; mf++)
            #pragma unroll
            for (int nf = 0; nf < 8; nf++)
                #pragma unroll
                for (int i = 0; i < 4; i++) S[mf][nf][i] = 0.f;
        #pragma unroll
        for (int kf = 0; kf < 8; kf++) {
            #pragma unroll
            for (int nf = 0; nf < 8; nf++) {
                uint32_t b[2];
                b[0] = Ks[(nf * 8 + g) * LDK + kf * 8 + tig    ];
                b[1] = Ks[(nf * 8 + g) * LDK + kf * 8 + tig + 4];
                mma8(S[0][nf], Qa[0][kf], b);
                mma8(S[1][nf], Qa[1][kf], b);
            }
        }

        // online softmax; after the sum, round S to tf32 in place
        #pragma unroll
        for (int mf = 0; mf < 2; mf++) {
            float mx0 = -1e30f, mx1 = -1e30f;
            #pragma unroll
            for (int nf = 0; nf < 8; nf++) {
                mx0 = fmaxf(mx0, fmaxf(S[mf][nf][0], S[mf][nf][1]));
                mx1 = fmaxf(mx1, fmaxf(S[mf][nf][2], S[mf][nf][3]));
            }
            mx0 = fmaxf(mx0, __shfl_xor_sync(0xffffffffu, mx0, 1));
            mx0 = fmaxf(mx0, __shfl_xor_sync(0xffffffffu, mx0, 2));
            mx1 = fmaxf(mx1, __shfl_xor_sync(0xffffffffu, mx1, 1));
            mx1 = fmaxf(mx1, __shfl_xor_sync(0xffffffffu, mx1, 2));
            const float mn0 = fmaxf(mr[mf][0], mx0), mn1 = fmaxf(mr[mf][1], mx1);
            const float cr0 = __expf(mr[mf][0] - mn0), cr1 = __expf(mr[mf][1] - mn1);
            mr[mf][0] = mn0; mr[mf][1] = mn1;
            float s0 = 0.f, s1 = 0.f;
            #pragma unroll
            for (int nf = 0; nf < 8; nf++) {
                float p0 = __expf(S[mf][nf][0] - mn0); s0 += p0;
                float p1 = __expf(S[mf][nf][1] - mn0); s0 += p1;
                float p2 = __expf(S[mf][nf][2] - mn1); s1 += p2;
                float p3 = __expf(S[mf][nf][3] - mn1); s1 += p3;
                S[mf][nf][0] = __uint_as_float(f2tf32(p0));
                S[mf][nf][1] = __uint_as_float(f2tf32(p1));
                S[mf][nf][2] = __uint_as_float(f2tf32(p2));
                S[mf][nf][3] = __uint_as_float(f2tf32(p3));
            }
            s0 += __shfl_xor_sync(0xffffffffu, s0, 1);
            s0 += __shfl_xor_sync(0xffffffffu, s0, 2);
            s1 += __shfl_xor_sync(0xffffffffu, s1, 1);
            s1 += __shfl_xor_sync(0xffffffffu, s1, 2);
            lr[mf][0] = lr[mf][0] * cr0 + s0;
            lr[mf][1] = lr[mf][1] * cr1 + s1;
            #pragma unroll
            for (int nf = 0; nf < 8; nf++) {
                O[mf][nf][0] *= cr0; O[mf][nf][1] *= cr0;
                O[mf][nf][2] *= cr1; O[mf][nf][3] *= cr1;
            }
        }

        // O += P @ V : A-frags built from S C-frags via warp shuffles.
        // P(row, kf*8+j) lives on lane (row-group g)*4 + (j>>1), reg parity j&1.
        #pragma unroll
        for (int kf = 0; kf < 8; kf++) {
            uint32_t a[2][4];
            #pragma unroll
            for (int mf = 0; mf < 2; mf++) {
                const uint32_t c0 = __float_as_uint(S[mf][kf][0]);
                const uint32_t c1 = __float_as_uint(S[mf][kf][1]);
                const uint32_t c2 = __float_as_uint(S[mf][kf][2]);
                const uint32_t c3 = __float_as_uint(S[mf][kf][3]);
                uint32_t t0, t1;
                t0 = __shfl_sync(0xffffffffu, c0, s0l);
                t1 = __shfl_sync(0xffffffffu, c1, s0l);
                a[mf][0] = par ? t1 : t0;                  // (g,     kf*8+tig)
                t0 = __shfl_sync(0xffffffffu, c2, s0l);
                t1 = __shfl_sync(0xffffffffu, c3, s0l);
                a[mf][1] = par ? t1 : t0;                  // (g+8,   kf*8+tig)
                t0 = __shfl_sync(0xffffffffu, c0, s2l);
                t1 = __shfl_sync(0xffffffffu, c1, s2l);
                a[mf][2] = par ? t1 : t0;                  // (g,   kf*8+tig+4)
                t0 = __shfl_sync(0xffffffffu, c2, s2l);
                t1 = __shfl_sync(0xffffffffu, c3, s2l);
                a[mf][3] = par ? t1 : t0;                  // (g+8, kf*8+tig+4)
            }
            #pragma unroll
            for (int nf = 0; nf < 8; nf++) {
                uint32_t b[2];
                b[0] = Vt[(nf * 8 + g) * LDK + kf * 8 + tig    ];
                b[1] = Vt[(nf * 8 + g) * LDK + kf * 8 + tig + 4];
                mma8(O[0][nf], a[0], b);
                mma8(O[1][nf], a[1], b);
            }
        }
    }

    // normalize + store to g_ctx (B,S,D)
    const int bb = bh >> 4, h = bh & 15;
    #pragma unroll
    for (int mf = 0; mf < 2; mf++) {
        const float i0 = 1.0f / lr[mf][0], i1 = 1.0f / lr[mf][1];
        const int s0r = qt * 256 + w * 32 + mf * 16 + g;
        const int s1r = s0r + 8;
        #pragma unroll
        for (int nf = 0; nf < 8; nf++) {
            const int col = h * 64 + nf * 8 + tig * 2;
            *(float2*)&g_ctx[(size_t)(bb * NS + s0r) * ND + col] =
                make_float2(O[mf][nf][0] * i0, O[mf][nf][1] * i0);
            *(float2*)&g_ctx[(size_t)(bb * NS + s1r) * ND + col] =
                make_float2(O[mf][nf][2] * i1, O[mf][nf][3] * i1);
        }
    }
}

// =====================================================================
extern "C" void kernel_launch(void* const* d_in, const int* in_sizes, int n_in,
                              void* d_out, int out_size)
{
    const float* x  = (const float*)d_in[0];
    const float* Wq = (const float*)d_in[1];
    const float* bq = (const float*)d_in[2];
    const float* Wk = (const float*)d_in[3];
    const float* bk = (const float*)d_in[4];
    const float* Wv = (const float*)d_in[5];
    const float* bv = (const float*)d_in[6];
    const float* Wo = (const float*)d_in[7];
    const float* bo = (const float*)d_in[8];
    float* out = (float*)d_out;

    dim3 gqkv(ND / 128, NTOK / 128, 3);
    gemm_tf32<1><<<gqkv, 128>>>(x, Wq, bq, Wk, bk, Wv, bv, nullptr);

    dim3 gat(NB * NH, NS / 256);
    flash_tf32<<<gat, 256>>>();

    dim3 go(ND / 128, NTOK / 128, 1);
    gemm_tf32<0><<<go, 128>>>(nullptr, Wo, bo, nullptr, nullptr, nullptr, nullptr, out);
}